// round 13
// baseline (speedup 1.0000x reference)
#include <cuda_runtime.h>
#include <cuda_fp16.h>
#include <cuda_bf16.h>
#include <cstdint>
#include <cstring>

// Problem dims (fixed by the reference)
#define NROWS   16384
#define INDIM   256
#define OUTDIM  128

// Stage-2 tiling
#define BM 128
#define BK 32
#define KT (NROWS / BK)      // 512

// smem (halfs): bufA[2] 128x40 fp16 (no B smem)
#define A_BUF_HALFS 5120     // 128 * 40
#define TILE_SMEM (2 * A_BUF_HALFS * 2)   // 20480 B
#define RED_SMEM  65536                   // split-K reduction (4 warps x 16KB)
#define SMEM_AGGR (RED_SMEM > TILE_SMEM ? RED_SMEM : TILE_SMEM)

// Intermediate h in fp16, k-pair interleaved: word(kp, n) = g_h2w[kp*128 + n]
__device__ __half g_h2[(size_t)NROWS * OUTDIM];

// One dynamic-smem declaration for the whole TU.
extern __shared__ char dyn_smem[];

// ---------------------------------------------------------------------------
__device__ __forceinline__ uint32_t smem_u32(const void* p) {
    uint32_t a;
    asm("{ .reg .u64 t; cvta.to.shared.u64 t, %1; cvt.u32.u64 %0, t; }" : "=r"(a) : "l"(p));
    return a;
}
__device__ __forceinline__ uint32_t f2tf32_rn(float f) {
    uint32_t u;
    asm("cvt.rna.tf32.f32 %0, %1;" : "=r"(u) : "f"(f));
    return u;
}
__device__ __forceinline__ void mma_tf32(float c[4], const uint32_t a[4], const uint32_t b[2]) {
    asm volatile(
        "mma.sync.aligned.m16n8k8.row.col.f32.tf32.tf32.f32 "
        "{%0,%1,%2,%3}, {%4,%5,%6,%7}, {%8,%9}, {%0,%1,%2,%3};"
        : "+f"(c[0]), "+f"(c[1]), "+f"(c[2]), "+f"(c[3])
        : "r"(a[0]), "r"(a[1]), "r"(a[2]), "r"(a[3]), "r"(b[0]), "r"(b[1]));
}
__device__ __forceinline__ void mma_f16(float c[4], const uint32_t a[4], const uint32_t b[2]) {
    asm volatile(
        "mma.sync.aligned.m16n8k16.row.col.f32.f16.f16.f32 "
        "{%0,%1,%2,%3}, {%4,%5,%6,%7}, {%8,%9}, {%0,%1,%2,%3};"
        : "+f"(c[0]), "+f"(c[1]), "+f"(c[2]), "+f"(c[3])
        : "r"(a[0]), "r"(a[1]), "r"(a[2]), "r"(a[3]), "r"(b[0]), "r"(b[1]));
}
__device__ __forceinline__ void cp_async16(uint32_t saddr, const void* g) {
    asm volatile("cp.async.cg.shared.global [%0], [%1], 16;" :: "r"(saddr), "l"(g));
}
__device__ __forceinline__ void cp_commit() { asm volatile("cp.async.commit_group;"); }
__device__ __forceinline__ void ldsm_x4(uint32_t r[4], uint32_t saddr) {
    asm volatile("ldmatrix.sync.aligned.m8n8.x4.shared.b16 {%0,%1,%2,%3}, [%4];"
                 : "=r"(r[0]), "=r"(r[1]), "=r"(r[2]), "=r"(r[3]) : "r"(saddr));
}

// ============================================================================
// Stage 1: h = x @ W^T + b  (tf32, RN both sides) -> g_h2 fp16 interleaved
// ============================================================================
#define A_STRIDE 36
__global__ __launch_bounds__(256, 1)
void gemm_lin(const float* __restrict__ x, const float* __restrict__ W,
              const float* __restrict__ bias) {
    float* smem = (float*)dyn_smem;
    float* As0 = smem;
    float* As1 = As0 + BM * A_STRIDE;
    float* Ws0 = As1 + BM * A_STRIDE;
    float* Ws1 = Ws0 + OUTDIM * A_STRIDE;

    const int tid  = threadIdx.x;
    const int lane = tid & 31, wid = tid >> 5;
    const int warpM = wid >> 2, warpN = wid & 3;
    const int bm = blockIdx.x;

    uint32_t sA0 = smem_u32(As0), sA1 = smem_u32(As1);
    uint32_t sW0 = smem_u32(Ws0), sW1 = smem_u32(Ws1);

    float c[4][4][4];
#pragma unroll
    for (int i = 0; i < 4; i++)
#pragma unroll
        for (int j = 0; j < 4; j++)
#pragma unroll
            for (int k = 0; k < 4; k++) c[i][j][k] = 0.0f;

    auto load36 = [&](uint32_t sbase, const float* src, int row0, int k0, int ldK) {
#pragma unroll
        for (int t = 0; t < 4; t++) {
            int idx = tid + t * 256;
            int r = idx >> 3, cc = (idx & 7) << 2;
            cp_async16(sbase + (uint32_t)(r * A_STRIDE + cc) * 4u,
                       src + (size_t)(row0 + r) * ldK + k0 + cc);
        }
    };

    load36(sA0, x, bm * BM, 0, INDIM);
    load36(sW0, W, 0, 0, INDIM);
    cp_commit();

    const int KTL = INDIM / BK; // 8
    for (int kt = 0; kt < KTL; kt++) {
        asm volatile("cp.async.wait_group 0;" ::: "memory");
        __syncthreads();
        if (kt + 1 < KTL) {
            load36(((kt + 1) & 1) ? sA1 : sA0, x, bm * BM, (kt + 1) * BK, INDIM);
            load36(((kt + 1) & 1) ? sW1 : sW0, W, 0, (kt + 1) * BK, INDIM);
            cp_commit();
        }
        const float* As = (kt & 1) ? As1 : As0;
        const float* Ws = (kt & 1) ? Ws1 : Ws0;

#pragma unroll
        for (int kk = 0; kk < BK; kk += 8) {
            uint32_t af[4][4];
#pragma unroll
            for (int mi = 0; mi < 4; mi++) {
                int r  = warpM * 64 + mi * 16 + (lane >> 2);
                int cc = kk + (lane & 3);
                af[mi][0] = f2tf32_rn(As[r * A_STRIDE + cc]);
                af[mi][1] = f2tf32_rn(As[(r + 8) * A_STRIDE + cc]);
                af[mi][2] = f2tf32_rn(As[r * A_STRIDE + cc + 4]);
                af[mi][3] = f2tf32_rn(As[(r + 8) * A_STRIDE + cc + 4]);
            }
            uint32_t bf[4][2];
#pragma unroll
            for (int ni = 0; ni < 4; ni++) {
                int n = warpN * 32 + ni * 8 + (lane >> 2);
                int k = kk + (lane & 3);
                bf[ni][0] = f2tf32_rn(Ws[n * A_STRIDE + k]);
                bf[ni][1] = f2tf32_rn(Ws[n * A_STRIDE + k + 4]);
            }
#pragma unroll
            for (int mi = 0; mi < 4; mi++)
#pragma unroll
                for (int ni = 0; ni < 4; ni++) mma_tf32(c[mi][ni], af[mi], bf[ni]);
        }
        __syncthreads();
    }

    // Epilogue: bias add, fp16-RN, store into k-pair-interleaved g_h2.
#pragma unroll
    for (int ni = 0; ni < 4; ni++) {
        int cn = warpN * 32 + ni * 8 + ((lane & 3) << 1);
        float2 bb = *(const float2*)(bias + cn);
#pragma unroll
        for (int mi = 0; mi < 4; mi++) {
            int r0 = bm * BM + warpM * 64 + mi * 16 + (lane >> 2);
            int r1 = r0 + 8;
            size_t b0 = (size_t)(r0 >> 1) * 256 + (r0 & 1);
            size_t b1 = (size_t)(r1 >> 1) * 256 + (r1 & 1);
            g_h2[b0 + (size_t)cn * 2]       = __float2half_rn(c[mi][ni][0] + bb.x);
            g_h2[b0 + (size_t)(cn + 1) * 2] = __float2half_rn(c[mi][ni][1] + bb.y);
            g_h2[b1 + (size_t)cn * 2]       = __float2half_rn(c[mi][ni][2] + bb.x);
            g_h2[b1 + (size_t)(cn + 1) * 2] = __float2half_rn(c[mi][ni][3] + bb.y);
        }
    }
}

// ============================================================================
// Stage 2: out = A_hat @ h, fp16 HMMA m16n8k16.
// 256 threads, 8 warps = 2(M) x 2(N) x 2(K-split). Warp tile 64x64; one
// m16n8k16 k-step per warp per BK=32 tile, 32 HMMA per warp per tile.
// A fragments: ldmatrix.x4 (4 per warp-tile, 2x duplication instead of 4x).
// B fragments: direct LDG.32 from L2-resident g_h2, 1-iter register prefetch.
// ============================================================================
struct ARegs { float4 v[4]; };   // 16 floats: rows (tid>>2), (tid>>2)+64; 8 k each

__device__ __forceinline__ void ldgA(ARegs& ra, const float* __restrict__ A,
                                     int bm, int kt, int tid) {
    const int row = tid >> 2, kc = (tid & 3) * 8;
    const float* p = A + (size_t)(bm * BM + row) * NROWS + kt * BK + kc;
    ra.v[0] = *(const float4*)p;
    ra.v[1] = *(const float4*)(p + 4);
    const float* q = p + (size_t)64 * NROWS;
    ra.v[2] = *(const float4*)q;
    ra.v[3] = *(const float4*)(q + 4);
}

__device__ __forceinline__ void stsA(__half* bufA, const ARegs& ra, int tid) {
    const int row = tid >> 2, kc = (tid & 3) * 8;
#pragma unroll
    for (int s = 0; s < 2; s++) {
        const float* f = (const float*)&ra.v[s * 2];
        __half2 h[4];
#pragma unroll
        for (int j = 0; j < 4; j++) h[j] = __floats2half2_rn(f[2 * j], f[2 * j + 1]);
        uint4 u;
        memcpy(&u, h, 16);
        *(uint4*)&bufA[(row + s * 64) * 40 + kc] = u;
    }
}

// B fragment LDG: bf[ni][r] for tile kt, straight from g_h2 (word view).
__device__ __forceinline__ void ldgB(uint32_t bf[8][2], int kt,
                                     int lane, int warpN, int warpK) {
    const uint32_t* gw = (const uint32_t*)g_h2;
    const int kp = kt * 16 + warpK * 8 + (lane & 3);
    const int n0 = warpN * 64 + (lane >> 2);
#pragma unroll
    for (int ni = 0; ni < 8; ni++) {
        const uint32_t* p = gw + (size_t)kp * 128 + n0 + ni * 8;
        bf[ni][0] = p[0];
        bf[ni][1] = p[4 * 128];
    }
}

__device__ __forceinline__ void computeTile(uint32_t saBase,
                                            const uint32_t bf[8][2],
                                            float c[4][8][4], int lane,
                                            int warpM, int warpK) {
    const int rbase = warpM * 64 + ((lane >> 3) & 1) * 8 + (lane & 7);
    const int kloc  = warpK * 16 + (lane >> 4) * 8;
    uint32_t af[4][4];
#pragma unroll
    for (int mi = 0; mi < 4; mi++) {
        uint32_t sa = saBase + (uint32_t)(((rbase + mi * 16) * 40 + kloc) * 2);
        ldsm_x4(af[mi], sa);
    }
#pragma unroll
    for (int mi = 0; mi < 4; mi++)
#pragma unroll
        for (int ni = 0; ni < 8; ni++) mma_f16(c[mi][ni], af[mi], bf[ni]);
}

__global__ __launch_bounds__(256, 1)
void gemm_aggr(const float* __restrict__ A, float* __restrict__ out) {
    __half* sm = (__half*)dyn_smem;
    __half* bufA[2] = { sm, sm + A_BUF_HALFS };
    const uint32_t sa[2] = { smem_u32(bufA[0]), smem_u32(bufA[1]) };

    const int tid  = threadIdx.x;
    const int lane = tid & 31, wid = tid >> 5;     // wid 0..7
    const int warpK = wid >> 2;                    // 0,1
    const int warpM = (wid >> 1) & 1;              // 0,1
    const int warpN = wid & 1;                     // 0,1
    const int bm = blockIdx.x;

    float c[4][8][4];
#pragma unroll
    for (int i = 0; i < 4; i++)
#pragma unroll
        for (int j = 0; j < 8; j++)
#pragma unroll
            for (int k = 0; k < 4; k++) c[i][j][k] = 0.0f;

    // Prologue: A tile0 -> smem, A tile1 -> regs, B tile0 -> frag regs.
    ARegs ra;
    uint32_t bfr[2][8][2];
    {
        ARegs t0;
        ldgA(t0, A, bm, 0, tid);
        ldgB(bfr[0], 0, lane, warpN, warpK);
        stsA(bufA[0], t0, tid);
        ldgA(ra, A, bm, 1, tid);
        __syncthreads();
    }

    for (int kt = 0; kt < KT; kt++) {
        const int n1 = (kt + 1 < KT) ? kt + 1 : KT - 1;
        const int n2 = (kt + 2 < KT) ? kt + 2 : KT - 1;

        // Prefetches for future tiles (latency covered by compute below).
        stsA(bufA[(kt + 1) & 1], ra, tid);                 // A tile kt+1
        ldgA(ra, A, bm, n2, tid);                          // A tile kt+2 -> regs
        ldgB(bfr[(kt + 1) & 1], n1, lane, warpN, warpK);   // B tile kt+1 -> regs

        computeTile(sa[kt & 1], bfr[kt & 1], c, lane, warpM, warpK);

        __syncthreads();   // A double-buffer epoch boundary
    }

    // ---- split-K reduction: warpK=1 -> smem, warpK=0 adds & stores ----
    float* red = (float*)dyn_smem;        // 4 warps * 4096 floats = 64 KB
    float4* cf4 = (float4*)&c[0][0][0];   // 32 float4 per thread
    __syncthreads();
    if (warpK == 1) {
        float4* dst = (float4*)(red + (wid - 4) * 4096);
#pragma unroll
        for (int i = 0; i < 32; i++) dst[i * 32 + lane] = cf4[i];
    }
    __syncthreads();
    if (warpK == 0) {
        const float4* src = (const float4*)(red + wid * 4096);
#pragma unroll
        for (int i = 0; i < 32; i++) {
            float4 v = src[i * 32 + lane];
            cf4[i].x += v.x; cf4[i].y += v.y; cf4[i].z += v.z; cf4[i].w += v.w;
        }
#pragma unroll
        for (int mi = 0; mi < 4; mi++)
#pragma unroll
            for (int ni = 0; ni < 8; ni++) {
                int r  = bm * BM + warpM * 64 + mi * 16 + (lane >> 2);
                int cn = warpN * 64 + ni * 8 + ((lane & 3) << 1);
                *(float2*)&out[(size_t)r * OUTDIM + cn] =
                    make_float2(c[mi][ni][0], c[mi][ni][1]);
                *(float2*)&out[(size_t)(r + 8) * OUTDIM + cn] =
                    make_float2(c[mi][ni][2], c[mi][ni][3]);
            }
    }
}

static const int SMEM_LIN = (2 * BM * A_STRIDE + 2 * OUTDIM * A_STRIDE) * 4;  // 73728

extern "C" void kernel_launch(void* const* d_in, const int* in_sizes, int n_in,
                              void* d_out, int out_size) {
    const float* x     = (const float*)d_in[0];
    const float* A_hat = (const float*)d_in[1];
    const float* W     = (const float*)d_in[2];
    const float* b     = (const float*)d_in[3];
    float* out = (float*)d_out;

    cudaFuncSetAttribute(gemm_lin,  cudaFuncAttributeMaxDynamicSharedMemorySize, SMEM_LIN);
    cudaFuncSetAttribute(gemm_aggr, cudaFuncAttributeMaxDynamicSharedMemorySize, SMEM_AGGR);

    gemm_lin<<<NROWS / BM, 256, SMEM_LIN>>>(x, W, b);
    gemm_aggr<<<NROWS / BM, 256, SMEM_AGGR>>>(A_hat, out);
}

// round 14
// speedup vs baseline: 1.5635x; 1.5635x over previous
#include <cuda_runtime.h>
#include <cuda_fp16.h>
#include <cuda_bf16.h>
#include <cstdint>
#include <cstring>

// Problem dims (fixed by the reference)
#define NROWS   16384
#define INDIM   256
#define OUTDIM  128

// Stage-2 tiling
#define BM 128
#define BK 32
#define KT (NROWS / BK)      // 512

// smem (halfs): bufA[3] 128x40 fp16 ring (no B smem)
#define A_BUF_HALFS 5120     // 128 * 40
#define TILE_SMEM (3 * A_BUF_HALFS * 2)   // 30720 B
#define RED_SMEM  65536                   // split-K reduction
#define SMEM_AGGR (RED_SMEM > TILE_SMEM ? RED_SMEM : TILE_SMEM)

// Intermediate h in fp16, k-pair interleaved: word(kp, n) = g_h2w[kp*128 + n]
__device__ __half g_h2[(size_t)NROWS * OUTDIM];

// One dynamic-smem declaration for the whole TU.
extern __shared__ char dyn_smem[];

// ---------------------------------------------------------------------------
__device__ __forceinline__ uint32_t smem_u32(const void* p) {
    uint32_t a;
    asm("{ .reg .u64 t; cvta.to.shared.u64 t, %1; cvt.u32.u64 %0, t; }" : "=r"(a) : "l"(p));
    return a;
}
__device__ __forceinline__ uint32_t f2tf32_rn(float f) {
    uint32_t u;
    asm("cvt.rna.tf32.f32 %0, %1;" : "=r"(u) : "f"(f));
    return u;
}
__device__ __forceinline__ void mma_tf32(float c[4], const uint32_t a[4], const uint32_t b[2]) {
    asm volatile(
        "mma.sync.aligned.m16n8k8.row.col.f32.tf32.tf32.f32 "
        "{%0,%1,%2,%3}, {%4,%5,%6,%7}, {%8,%9}, {%0,%1,%2,%3};"
        : "+f"(c[0]), "+f"(c[1]), "+f"(c[2]), "+f"(c[3])
        : "r"(a[0]), "r"(a[1]), "r"(a[2]), "r"(a[3]), "r"(b[0]), "r"(b[1]));
}
__device__ __forceinline__ void mma_f16(float c[4], const uint32_t a[4], const uint32_t b[2]) {
    asm volatile(
        "mma.sync.aligned.m16n8k16.row.col.f32.f16.f16.f32 "
        "{%0,%1,%2,%3}, {%4,%5,%6,%7}, {%8,%9}, {%0,%1,%2,%3};"
        : "+f"(c[0]), "+f"(c[1]), "+f"(c[2]), "+f"(c[3])
        : "r"(a[0]), "r"(a[1]), "r"(a[2]), "r"(a[3]), "r"(b[0]), "r"(b[1]));
}
__device__ __forceinline__ void cp_async16(uint32_t saddr, const void* g) {
    asm volatile("cp.async.cg.shared.global [%0], [%1], 16;" :: "r"(saddr), "l"(g));
}
__device__ __forceinline__ void cp_commit() { asm volatile("cp.async.commit_group;"); }
__device__ __forceinline__ void ldsm_x4(uint32_t r[4], uint32_t saddr) {
    asm volatile("ldmatrix.sync.aligned.m8n8.x4.shared.b16 {%0,%1,%2,%3}, [%4];"
                 : "=r"(r[0]), "=r"(r[1]), "=r"(r[2]), "=r"(r[3]) : "r"(saddr));
}

// ============================================================================
// Stage 1: h = x @ W^T + b  (tf32, RN both sides) -> g_h2 fp16 interleaved
// ============================================================================
#define A_STRIDE 36
__global__ __launch_bounds__(256, 1)
void gemm_lin(const float* __restrict__ x, const float* __restrict__ W,
              const float* __restrict__ bias) {
    float* smem = (float*)dyn_smem;
    float* As0 = smem;
    float* As1 = As0 + BM * A_STRIDE;
    float* Ws0 = As1 + BM * A_STRIDE;
    float* Ws1 = Ws0 + OUTDIM * A_STRIDE;

    const int tid  = threadIdx.x;
    const int lane = tid & 31, wid = tid >> 5;
    const int warpM = wid >> 2, warpN = wid & 3;
    const int bm = blockIdx.x;

    uint32_t sA0 = smem_u32(As0), sA1 = smem_u32(As1);
    uint32_t sW0 = smem_u32(Ws0), sW1 = smem_u32(Ws1);

    float c[4][4][4];
#pragma unroll
    for (int i = 0; i < 4; i++)
#pragma unroll
        for (int j = 0; j < 4; j++)
#pragma unroll
            for (int k = 0; k < 4; k++) c[i][j][k] = 0.0f;

    auto load36 = [&](uint32_t sbase, const float* src, int row0, int k0, int ldK) {
#pragma unroll
        for (int t = 0; t < 4; t++) {
            int idx = tid + t * 256;
            int r = idx >> 3, cc = (idx & 7) << 2;
            cp_async16(sbase + (uint32_t)(r * A_STRIDE + cc) * 4u,
                       src + (size_t)(row0 + r) * ldK + k0 + cc);
        }
    };

    load36(sA0, x, bm * BM, 0, INDIM);
    load36(sW0, W, 0, 0, INDIM);
    cp_commit();

    const int KTL = INDIM / BK; // 8
    for (int kt = 0; kt < KTL; kt++) {
        asm volatile("cp.async.wait_group 0;" ::: "memory");
        __syncthreads();
        if (kt + 1 < KTL) {
            load36(((kt + 1) & 1) ? sA1 : sA0, x, bm * BM, (kt + 1) * BK, INDIM);
            load36(((kt + 1) & 1) ? sW1 : sW0, W, 0, (kt + 1) * BK, INDIM);
            cp_commit();
        }
        const float* As = (kt & 1) ? As1 : As0;
        const float* Ws = (kt & 1) ? Ws1 : Ws0;

#pragma unroll
        for (int kk = 0; kk < BK; kk += 8) {
            uint32_t af[4][4];
#pragma unroll
            for (int mi = 0; mi < 4; mi++) {
                int r  = warpM * 64 + mi * 16 + (lane >> 2);
                int cc = kk + (lane & 3);
                af[mi][0] = f2tf32_rn(As[r * A_STRIDE + cc]);
                af[mi][1] = f2tf32_rn(As[(r + 8) * A_STRIDE + cc]);
                af[mi][2] = f2tf32_rn(As[r * A_STRIDE + cc + 4]);
                af[mi][3] = f2tf32_rn(As[(r + 8) * A_STRIDE + cc + 4]);
            }
            uint32_t bf[4][2];
#pragma unroll
            for (int ni = 0; ni < 4; ni++) {
                int n = warpN * 32 + ni * 8 + (lane >> 2);
                int k = kk + (lane & 3);
                bf[ni][0] = f2tf32_rn(Ws[n * A_STRIDE + k]);
                bf[ni][1] = f2tf32_rn(Ws[n * A_STRIDE + k + 4]);
            }
#pragma unroll
            for (int mi = 0; mi < 4; mi++)
#pragma unroll
                for (int ni = 0; ni < 4; ni++) mma_tf32(c[mi][ni], af[mi], bf[ni]);
        }
        __syncthreads();
    }

    // Epilogue: bias add, fp16-RN, store into k-pair-interleaved g_h2.
#pragma unroll
    for (int ni = 0; ni < 4; ni++) {
        int cn = warpN * 32 + ni * 8 + ((lane & 3) << 1);
        float2 bb = *(const float2*)(bias + cn);
#pragma unroll
        for (int mi = 0; mi < 4; mi++) {
            int r0 = bm * BM + warpM * 64 + mi * 16 + (lane >> 2);
            int r1 = r0 + 8;
            size_t b0 = (size_t)(r0 >> 1) * 256 + (r0 & 1);
            size_t b1 = (size_t)(r1 >> 1) * 256 + (r1 & 1);
            g_h2[b0 + (size_t)cn * 2]       = __float2half_rn(c[mi][ni][0] + bb.x);
            g_h2[b0 + (size_t)(cn + 1) * 2] = __float2half_rn(c[mi][ni][1] + bb.y);
            g_h2[b1 + (size_t)cn * 2]       = __float2half_rn(c[mi][ni][2] + bb.x);
            g_h2[b1 + (size_t)(cn + 1) * 2] = __float2half_rn(c[mi][ni][3] + bb.y);
        }
    }
}

// ============================================================================
// Stage 2: out = A_hat @ h, fp16 HMMA m16n8k16.
// 512 threads, 16 warps = 2(M) x 4(N) x 2(K-split). Warp tile 64x32.
// A: 3-stage smem ring + HALF-TILE fragment pipeline (two 8-reg af buffers):
//   every LDSM loads fragments consumed one MMA-burst later, so LDSM latency
//   and prefetch ops hide under HMMA. Register count stays at R12's 128.
// B: direct LDG.32 from L2-resident g_h2, 1-iter register prefetch (as R12).
// ============================================================================
struct ARegs { float4 v[2]; };   // 8 floats: row tid>>2, k (tid&3)*8 .. +7

__device__ __forceinline__ void ldgA(ARegs& ra, const float* __restrict__ A,
                                     int bm, int kt, int tid) {
    const int row = tid >> 2, kc = (tid & 3) * 8;
    const float* p = A + (size_t)(bm * BM + row) * NROWS + kt * BK + kc;
    ra.v[0] = *(const float4*)p;
    ra.v[1] = *(const float4*)(p + 4);
}

__device__ __forceinline__ void stsA(__half* bufA, const ARegs& ra, int tid) {
    const int row = tid >> 2, kc = (tid & 3) * 8;
    const float* f = (const float*)&ra.v[0];
    __half2 h[4];
#pragma unroll
    for (int j = 0; j < 4; j++) h[j] = __floats2half2_rn(f[2 * j], f[2 * j + 1]);
    uint4 u;
    memcpy(&u, h, 16);
    *(uint4*)&bufA[row * 40 + kc] = u;
}

// B fragment LDG: bf[ni][r] for tile kt, straight from g_h2 (word view).
__device__ __forceinline__ void ldgB(uint32_t bf[4][2], int kt,
                                     int lane, int warpN, int warpK) {
    const uint32_t* gw = (const uint32_t*)g_h2;
    const int kp = kt * 16 + warpK * 8 + (lane & 3);
    const int n0 = warpN * 32 + (lane >> 2);
#pragma unroll
    for (int ni = 0; ni < 4; ni++) {
        const uint32_t* p = gw + (size_t)kp * 128 + n0 + ni * 8;
        bf[ni][0] = p[0];
        bf[ni][1] = p[4 * 128];
    }
}

// Load fragments for HALF a warp tile (mi0, mi0+1) via 2x ldmatrix.x4.
__device__ __forceinline__ void ldsmHalf(uint32_t af[2][4], uint32_t saBase,
                                         int lane, int warpM, int warpK, int mi0) {
    const int rbase = warpM * 64 + mi0 * 16 + ((lane >> 3) & 1) * 8 + (lane & 7);
    const int kloc  = warpK * 16 + (lane >> 4) * 8;
#pragma unroll
    for (int mi = 0; mi < 2; mi++) {
        uint32_t sa = saBase + (uint32_t)(((rbase + mi * 16) * 40 + kloc) * 2);
        ldsm_x4(af[mi], sa);
    }
}

__device__ __forceinline__ void mmaHalf(float c[4][4][4], const uint32_t af[2][4],
                                        const uint32_t bf[4][2], int mi0) {
#pragma unroll
    for (int mi = 0; mi < 2; mi++)
#pragma unroll
        for (int ni = 0; ni < 4; ni++) mma_f16(c[mi0 + mi][ni], af[mi], bf[ni]);
}

__global__ __launch_bounds__(512, 1)
void gemm_aggr(const float* __restrict__ A, float* __restrict__ out) {
    __half* sm = (__half*)dyn_smem;
    __half* bufA[3] = { sm, sm + A_BUF_HALFS, sm + 2 * A_BUF_HALFS };
    const uint32_t sa[3] = { smem_u32(bufA[0]), smem_u32(bufA[1]), smem_u32(bufA[2]) };

    const int tid  = threadIdx.x;
    const int lane = tid & 31, wid = tid >> 5;     // wid 0..15
    const int warpK = wid >> 3;                    // 0,1
    const int warpM = (wid >> 2) & 1;              // 0,1
    const int warpN = wid & 3;                     // 0..3
    const int bm = blockIdx.x;

    float c[4][4][4];
#pragma unroll
    for (int i = 0; i < 4; i++)
#pragma unroll
        for (int j = 0; j < 4; j++)
#pragma unroll
            for (int k = 0; k < 4; k++) c[i][j][k] = 0.0f;

    // Prologue: A tiles 0,1 -> smem slots 0,1; tile 2 -> regs; B tile 0 -> regs.
    ARegs ra;
    uint32_t bfr[2][4][2];
    uint32_t afP[2][4], afQ[2][4];
    {
        ARegs t;
        ldgA(t, A, bm, 0, tid);  stsA(bufA[0], t, tid);
        ldgA(t, A, bm, 1, tid);  stsA(bufA[1], t, tid);
        ldgA(ra, A, bm, 2, tid);
        ldgB(bfr[0], 0, lane, warpN, warpK);
        __syncthreads();
        ldsmHalf(afP, sa[0], lane, warpM, warpK, 0);   // (tile0, h0)
    }

    int s_cur = 0, s_nxt = 1, s_wr = 2;
    for (int kt = 0; kt < KT; kt++) {
        const int n1 = (kt + 1 < KT) ? kt + 1 : KT - 1;
        const int n3 = (kt + 3 < KT) ? kt + 3 : KT - 1;

        // h1 fragments of the current tile (independent of the h0 MMA below).
        ldsmHalf(afQ, sa[s_cur], lane, warpM, warpK, 2);

        // MMA on h0 (fragments loaded one phase earlier).
        mmaHalf(c, afP, bfr[kt & 1], 0);

        // Prefetches (hide under the MMA bursts around them).
        stsA(bufA[s_wr], ra, tid);                        // A tile kt+2 -> ring
        ldgA(ra, A, bm, n3, tid);                         // A tile kt+3 -> regs
        ldgB(bfr[(kt + 1) & 1], n1, lane, warpN, warpK);  // B tile kt+1 -> regs

        // h0 fragments of the NEXT tile (slot filled at kt-1, barrier passed).
        ldsmHalf(afP, sa[s_nxt], lane, warpM, warpK, 0);

        // MMA on h1.
        mmaHalf(c, afQ, bfr[kt & 1], 2);

        __syncthreads();   // A ring epoch boundary

        int t = s_cur; s_cur = s_nxt; s_nxt = s_wr; s_wr = t;
    }

    // ---- split-K reduction: warpK=1 -> smem, warpK=0 adds & stores ----
    float* red = (float*)dyn_smem;        // 8 warps * 2048 floats = 64 KB
    float4* cf4 = (float4*)&c[0][0][0];   // 16 float4 per thread
    __syncthreads();
    if (warpK == 1) {
        float4* dst = (float4*)(red + (wid - 8) * 2048);
#pragma unroll
        for (int i = 0; i < 16; i++) dst[i * 32 + lane] = cf4[i];
    }
    __syncthreads();
    if (warpK == 0) {
        const float4* src = (const float4*)(red + wid * 2048);
#pragma unroll
        for (int i = 0; i < 16; i++) {
            float4 v = src[i * 32 + lane];
            cf4[i].x += v.x; cf4[i].y += v.y; cf4[i].z += v.z; cf4[i].w += v.w;
        }
#pragma unroll
        for (int mi = 0; mi < 4; mi++)
#pragma unroll
            for (int ni = 0; ni < 4; ni++) {
                int r  = bm * BM + warpM * 64 + mi * 16 + (lane >> 2);
                int cn = warpN * 32 + ni * 8 + ((lane & 3) << 1);
                *(float2*)&out[(size_t)r * OUTDIM + cn] =
                    make_float2(c[mi][ni][0], c[mi][ni][1]);
                *(float2*)&out[(size_t)(r + 8) * OUTDIM + cn] =
                    make_float2(c[mi][ni][2], c[mi][ni][3]);
            }
    }
}

static const int SMEM_LIN = (2 * BM * A_STRIDE + 2 * OUTDIM * A_STRIDE) * 4;  // 73728

extern "C" void kernel_launch(void* const* d_in, const int* in_sizes, int n_in,
                              void* d_out, int out_size) {
    const float* x     = (const float*)d_in[0];
    const float* A_hat = (const float*)d_in[1];
    const float* W     = (const float*)d_in[2];
    const float* b     = (const float*)d_in[3];
    float* out = (float*)d_out;

    cudaFuncSetAttribute(gemm_lin,  cudaFuncAttributeMaxDynamicSharedMemorySize, SMEM_LIN);
    cudaFuncSetAttribute(gemm_aggr, cudaFuncAttributeMaxDynamicSharedMemorySize, SMEM_AGGR);

    gemm_lin<<<NROWS / BM, 256, SMEM_LIN>>>(x, W, b);
    gemm_aggr<<<NROWS / BM, 512, SMEM_AGGR>>>(A_hat, out);
}

// round 15
// speedup vs baseline: 1.9731x; 1.2620x over previous
#include <cuda_runtime.h>
#include <cuda_fp16.h>
#include <cuda_bf16.h>
#include <cstdint>
#include <cstring>

// Problem dims (fixed by the reference)
#define NROWS   16384
#define INDIM   256
#define OUTDIM  128

// Stage-2 tiling
#define BM 128
#define BK 32
#define KT (NROWS / BK)      // 512
#define KSPLIT 2
#define KT_PER (KT / KSPLIT) // 256

// smem (halfs): bufA[2] 128x40 fp16 (no B smem, no reduction smem)
#define A_BUF_HALFS 5120     // 128 * 40
#define SMEM_AGGR (2 * A_BUF_HALFS * 2)   // 20480 B per CTA

// Intermediate h in fp16, k-pair interleaved: word(kp, n) = g_h2w[kp*128 + n]
__device__ __half g_h2[(size_t)NROWS * OUTDIM];
// Split-K partials (fp32)
__device__ float g_part[KSPLIT][(size_t)NROWS * OUTDIM];

// One dynamic-smem declaration for the whole TU.
extern __shared__ char dyn_smem[];

// ---------------------------------------------------------------------------
__device__ __forceinline__ uint32_t smem_u32(const void* p) {
    uint32_t a;
    asm("{ .reg .u64 t; cvta.to.shared.u64 t, %1; cvt.u32.u64 %0, t; }" : "=r"(a) : "l"(p));
    return a;
}
__device__ __forceinline__ uint32_t f2tf32_rn(float f) {
    uint32_t u;
    asm("cvt.rna.tf32.f32 %0, %1;" : "=r"(u) : "f"(f));
    return u;
}
__device__ __forceinline__ void mma_tf32(float c[4], const uint32_t a[4], const uint32_t b[2]) {
    asm volatile(
        "mma.sync.aligned.m16n8k8.row.col.f32.tf32.tf32.f32 "
        "{%0,%1,%2,%3}, {%4,%5,%6,%7}, {%8,%9}, {%0,%1,%2,%3};"
        : "+f"(c[0]), "+f"(c[1]), "+f"(c[2]), "+f"(c[3])
        : "r"(a[0]), "r"(a[1]), "r"(a[2]), "r"(a[3]), "r"(b[0]), "r"(b[1]));
}
__device__ __forceinline__ void mma_f16(float c[4], const uint32_t a[4], const uint32_t b[2]) {
    asm volatile(
        "mma.sync.aligned.m16n8k16.row.col.f32.f16.f16.f32 "
        "{%0,%1,%2,%3}, {%4,%5,%6,%7}, {%8,%9}, {%0,%1,%2,%3};"
        : "+f"(c[0]), "+f"(c[1]), "+f"(c[2]), "+f"(c[3])
        : "r"(a[0]), "r"(a[1]), "r"(a[2]), "r"(a[3]), "r"(b[0]), "r"(b[1]));
}
__device__ __forceinline__ void cp_async16(uint32_t saddr, const void* g) {
    asm volatile("cp.async.cg.shared.global [%0], [%1], 16;" :: "r"(saddr), "l"(g));
}
__device__ __forceinline__ void cp_commit() { asm volatile("cp.async.commit_group;"); }
__device__ __forceinline__ void ldsm_x4(uint32_t r[4], uint32_t saddr) {
    asm volatile("ldmatrix.sync.aligned.m8n8.x4.shared.b16 {%0,%1,%2,%3}, [%4];"
                 : "=r"(r[0]), "=r"(r[1]), "=r"(r[2]), "=r"(r[3]) : "r"(saddr));
}

// ============================================================================
// Stage 1: h = x @ W^T + b  (tf32, RN both sides) -> g_h2 fp16 interleaved
// ============================================================================
#define A_STRIDE 36
__global__ __launch_bounds__(256, 1)
void gemm_lin(const float* __restrict__ x, const float* __restrict__ W,
              const float* __restrict__ bias) {
    float* smem = (float*)dyn_smem;
    float* As0 = smem;
    float* As1 = As0 + BM * A_STRIDE;
    float* Ws0 = As1 + BM * A_STRIDE;
    float* Ws1 = Ws0 + OUTDIM * A_STRIDE;

    const int tid  = threadIdx.x;
    const int lane = tid & 31, wid = tid >> 5;
    const int warpM = wid >> 2, warpN = wid & 3;
    const int bm = blockIdx.x;

    uint32_t sA0 = smem_u32(As0), sA1 = smem_u32(As1);
    uint32_t sW0 = smem_u32(Ws0), sW1 = smem_u32(Ws1);

    float c[4][4][4];
#pragma unroll
    for (int i = 0; i < 4; i++)
#pragma unroll
        for (int j = 0; j < 4; j++)
#pragma unroll
            for (int k = 0; k < 4; k++) c[i][j][k] = 0.0f;

    auto load36 = [&](uint32_t sbase, const float* src, int row0, int k0, int ldK) {
#pragma unroll
        for (int t = 0; t < 4; t++) {
            int idx = tid + t * 256;
            int r = idx >> 3, cc = (idx & 7) << 2;
            cp_async16(sbase + (uint32_t)(r * A_STRIDE + cc) * 4u,
                       src + (size_t)(row0 + r) * ldK + k0 + cc);
        }
    };

    load36(sA0, x, bm * BM, 0, INDIM);
    load36(sW0, W, 0, 0, INDIM);
    cp_commit();

    const int KTL = INDIM / BK; // 8
    for (int kt = 0; kt < KTL; kt++) {
        asm volatile("cp.async.wait_group 0;" ::: "memory");
        __syncthreads();
        if (kt + 1 < KTL) {
            load36(((kt + 1) & 1) ? sA1 : sA0, x, bm * BM, (kt + 1) * BK, INDIM);
            load36(((kt + 1) & 1) ? sW1 : sW0, W, 0, (kt + 1) * BK, INDIM);
            cp_commit();
        }
        const float* As = (kt & 1) ? As1 : As0;
        const float* Ws = (kt & 1) ? Ws1 : Ws0;

#pragma unroll
        for (int kk = 0; kk < BK; kk += 8) {
            uint32_t af[4][4];
#pragma unroll
            for (int mi = 0; mi < 4; mi++) {
                int r  = warpM * 64 + mi * 16 + (lane >> 2);
                int cc = kk + (lane & 3);
                af[mi][0] = f2tf32_rn(As[r * A_STRIDE + cc]);
                af[mi][1] = f2tf32_rn(As[(r + 8) * A_STRIDE + cc]);
                af[mi][2] = f2tf32_rn(As[r * A_STRIDE + cc + 4]);
                af[mi][3] = f2tf32_rn(As[(r + 8) * A_STRIDE + cc + 4]);
            }
            uint32_t bf[4][2];
#pragma unroll
            for (int ni = 0; ni < 4; ni++) {
                int n = warpN * 32 + ni * 8 + (lane >> 2);
                int k = kk + (lane & 3);
                bf[ni][0] = f2tf32_rn(Ws[n * A_STRIDE + k]);
                bf[ni][1] = f2tf32_rn(Ws[n * A_STRIDE + k + 4]);
            }
#pragma unroll
            for (int mi = 0; mi < 4; mi++)
#pragma unroll
                for (int ni = 0; ni < 4; ni++) mma_tf32(c[mi][ni], af[mi], bf[ni]);
        }
        __syncthreads();
    }

    // Epilogue: bias add, fp16-RN, store into k-pair-interleaved g_h2.
#pragma unroll
    for (int ni = 0; ni < 4; ni++) {
        int cn = warpN * 32 + ni * 8 + ((lane & 3) << 1);
        float2 bb = *(const float2*)(bias + cn);
#pragma unroll
        for (int mi = 0; mi < 4; mi++) {
            int r0 = bm * BM + warpM * 64 + mi * 16 + (lane >> 2);
            int r1 = r0 + 8;
            size_t b0 = (size_t)(r0 >> 1) * 256 + (r0 & 1);
            size_t b1 = (size_t)(r1 >> 1) * 256 + (r1 & 1);
            g_h2[b0 + (size_t)cn * 2]       = __float2half_rn(c[mi][ni][0] + bb.x);
            g_h2[b0 + (size_t)(cn + 1) * 2] = __float2half_rn(c[mi][ni][1] + bb.y);
            g_h2[b1 + (size_t)cn * 2]       = __float2half_rn(c[mi][ni][2] + bb.x);
            g_h2[b1 + (size_t)(cn + 1) * 2] = __float2half_rn(c[mi][ni][3] + bb.y);
        }
    }
}

// ============================================================================
// Stage 2: out = A_hat @ h, fp16 HMMA m16n8k16, grid-level split-K.
// Grid (128, 2): CTA (bm, s) does k-tiles [s*256, s*256+256).
// 256 threads, 8 warps = 2(M) x 4(N); warp tile 64x32, both k16 halves
// in-warp (af regs reused). 2 CTAs/SM: occupancy hides LDSM/LDG latency.
// ============================================================================
struct ARegs { float4 v[4]; };   // 16 floats: row tid>>1, k (tid&1)*16 .. +15

__device__ __forceinline__ void ldgA(ARegs& ra, const float* __restrict__ A,
                                     int bm, int kt, int tid) {
    const int row = tid >> 1, kc = (tid & 1) * 16;
    const float* p = A + (size_t)(bm * BM + row) * NROWS + kt * BK + kc;
#pragma unroll
    for (int j = 0; j < 4; j++) ra.v[j] = *(const float4*)(p + 4 * j);
}

__device__ __forceinline__ void stsA(__half* bufA, const ARegs& ra, int tid) {
    const int row = tid >> 1, kc = (tid & 1) * 16;
    const float* f = (const float*)&ra.v[0];
    __half2 h[8];
#pragma unroll
    for (int j = 0; j < 8; j++) h[j] = __floats2half2_rn(f[2 * j], f[2 * j + 1]);
    uint4 u0, u1;
    memcpy(&u0, &h[0], 16);
    memcpy(&u1, &h[4], 16);
    *(uint4*)&bufA[row * 40 + kc]     = u0;
    *(uint4*)&bufA[row * 40 + kc + 8] = u1;
}

// B fragments for one k16 half of tile kt, straight from g_h2 (word view).
__device__ __forceinline__ void ldgB(uint32_t bf[4][2], int kt, int kh,
                                     int lane, int warpN) {
    const uint32_t* gw = (const uint32_t*)g_h2;
    const int kp = kt * 16 + kh * 8 + (lane & 3);
    const int n0 = warpN * 32 + (lane >> 2);
#pragma unroll
    for (int ni = 0; ni < 4; ni++) {
        const uint32_t* p = gw + (size_t)kp * 128 + n0 + ni * 8;
        bf[ni][0] = p[0];
        bf[ni][1] = p[4 * 128];
    }
}

__global__ __launch_bounds__(256, 2)
void gemm_aggr(const float* __restrict__ A) {
    __half* sm = (__half*)dyn_smem;
    __half* bufA[2] = { sm, sm + A_BUF_HALFS };
    const uint32_t sa[2] = { smem_u32(bufA[0]), smem_u32(bufA[1]) };

    const int tid  = threadIdx.x;
    const int lane = tid & 31, wid = tid >> 5;     // wid 0..7
    const int warpM = wid >> 2;                    // 0,1
    const int warpN = wid & 3;                     // 0..3
    const int bm = blockIdx.x;
    const int ks = blockIdx.y;                     // split-K segment
    const int kt0 = ks * KT_PER;

    float c[4][4][4];
#pragma unroll
    for (int i = 0; i < 4; i++)
#pragma unroll
        for (int j = 0; j < 4; j++)
#pragma unroll
            for (int k = 0; k < 4; k++) c[i][j][k] = 0.0f;

    // Prologue: A tile0 -> smem, A tile1 -> regs.
    ARegs ra;
    {
        ARegs t0;
        ldgA(t0, A, bm, kt0, tid);
        stsA(bufA[0], t0, tid);
        ldgA(ra, A, bm, kt0 + 1, tid);
        __syncthreads();
    }

    const int rbase = warpM * 64 + ((lane >> 3) & 1) * 8 + (lane & 7);

    for (int i = 0; i < KT_PER; i++) {
        const int kt = kt0 + i;
        const int n2 = (i + 2 < KT_PER) ? kt + 2 : kt0 + KT_PER - 1;

        // A pipeline upkeep (latency covered by compute + co-resident CTA).
        stsA(bufA[(i + 1) & 1], ra, tid);
        ldgA(ra, A, bm, n2, tid);

        // Both k16 halves; af regs reused across halves.
#pragma unroll
        for (int kh = 0; kh < 2; kh++) {
            uint32_t bf[4][2];
            ldgB(bf, kt, kh, lane, warpN);
            const int kloc = kh * 16 + (lane >> 4) * 8;
            uint32_t af[4][4];
#pragma unroll
            for (int mi = 0; mi < 4; mi++) {
                uint32_t sadr = sa[i & 1] +
                    (uint32_t)(((rbase + mi * 16) * 40 + kloc) * 2);
                ldsm_x4(af[mi], sadr);
            }
#pragma unroll
            for (int mi = 0; mi < 4; mi++)
#pragma unroll
                for (int ni = 0; ni < 4; ni++) mma_f16(c[mi][ni], af[mi], bf[ni]);
        }

        __syncthreads();   // A double-buffer epoch boundary
    }

    // Epilogue: store partial sums.
    float* part = g_part[ks];
#pragma unroll
    for (int mi = 0; mi < 4; mi++)
#pragma unroll
        for (int ni = 0; ni < 4; ni++) {
            int r  = bm * BM + warpM * 64 + mi * 16 + (lane >> 2);
            int cn = warpN * 32 + ni * 8 + ((lane & 3) << 1);
            *(float2*)&part[(size_t)r * OUTDIM + cn] =
                make_float2(c[mi][ni][0], c[mi][ni][1]);
            *(float2*)&part[(size_t)(r + 8) * OUTDIM + cn] =
                make_float2(c[mi][ni][2], c[mi][ni][3]);
        }
}

// ============================================================================
// Split-K reduce: out = part0 + part1  (2M fp32 elements, float4-vectorized)
// ============================================================================
__global__ __launch_bounds__(256, 1)
void reduce_k(float* __restrict__ out) {
    const size_t i = ((size_t)blockIdx.x * 256 + threadIdx.x) * 4;
    float4 a = *(const float4*)&g_part[0][i];
    float4 b = *(const float4*)&g_part[1][i];
    *(float4*)&out[i] = make_float4(a.x + b.x, a.y + b.y, a.z + b.z, a.w + b.w);
}

static const int SMEM_LIN = (2 * BM * A_STRIDE + 2 * OUTDIM * A_STRIDE) * 4;  // 73728

extern "C" void kernel_launch(void* const* d_in, const int* in_sizes, int n_in,
                              void* d_out, int out_size) {
    const float* x     = (const float*)d_in[0];
    const float* A_hat = (const float*)d_in[1];
    const float* W     = (const float*)d_in[2];
    const float* b     = (const float*)d_in[3];
    float* out = (float*)d_out;

    cudaFuncSetAttribute(gemm_lin,  cudaFuncAttributeMaxDynamicSharedMemorySize, SMEM_LIN);
    cudaFuncSetAttribute(gemm_aggr, cudaFuncAttributeMaxDynamicSharedMemorySize, SMEM_AGGR);

    gemm_lin<<<NROWS / BM, 256, SMEM_LIN>>>(x, W, b);
    gemm_aggr<<<dim3(NROWS / BM, KSPLIT), 256, SMEM_AGGR>>>(A_hat);
    reduce_k<<<(NROWS * OUTDIM) / (256 * 4), 256>>>(out);
}

// round 16
// speedup vs baseline: 2.3279x; 1.1798x over previous
#include <cuda_runtime.h>
#include <cuda_fp16.h>
#include <cuda_bf16.h>
#include <cstdint>
#include <cstring>

// Problem dims (fixed by the reference)
#define NROWS   16384
#define INDIM   256
#define OUTDIM  128

// Stage-2 tiling
#define BM 128
#define BK 32
#define KT (NROWS / BK)      // 512

// smem (halfs): bufA[2] 128x40, bufB[2] 128(n) x 40 (32 k halfs + pad)
#define A_BUF_HALFS 5120     // 128 * 40
#define B_BUF_HALFS 5120     // 128 * 40
#define TILE_SMEM ((2 * A_BUF_HALFS + 2 * B_BUF_HALFS) * 2)  // 40960 B
#define RED_SMEM  65536
#define SMEM_AGGR (RED_SMEM > TILE_SMEM ? RED_SMEM : TILE_SMEM)

// Intermediate h TRANSPOSED in fp16: g_hT[o * NROWS + row]
__device__ __half g_hT[(size_t)OUTDIM * NROWS];

// One dynamic-smem declaration for the whole TU.
extern __shared__ char dyn_smem[];

// ---------------------------------------------------------------------------
__device__ __forceinline__ uint32_t smem_u32(const void* p) {
    uint32_t a;
    asm("{ .reg .u64 t; cvta.to.shared.u64 t, %1; cvt.u32.u64 %0, t; }" : "=r"(a) : "l"(p));
    return a;
}
__device__ __forceinline__ uint32_t f2tf32_rn(float f) {
    uint32_t u;
    asm("cvt.rna.tf32.f32 %0, %1;" : "=r"(u) : "f"(f));
    return u;
}
__device__ __forceinline__ void mma_tf32(float c[4], const uint32_t a[4], const uint32_t b[2]) {
    asm volatile(
        "mma.sync.aligned.m16n8k8.row.col.f32.tf32.tf32.f32 "
        "{%0,%1,%2,%3}, {%4,%5,%6,%7}, {%8,%9}, {%0,%1,%2,%3};"
        : "+f"(c[0]), "+f"(c[1]), "+f"(c[2]), "+f"(c[3])
        : "r"(a[0]), "r"(a[1]), "r"(a[2]), "r"(a[3]), "r"(b[0]), "r"(b[1]));
}
__device__ __forceinline__ void mma_f16(float c[4], const uint32_t a[4], const uint32_t b[2]) {
    asm volatile(
        "mma.sync.aligned.m16n8k16.row.col.f32.f16.f16.f32 "
        "{%0,%1,%2,%3}, {%4,%5,%6,%7}, {%8,%9}, {%0,%1,%2,%3};"
        : "+f"(c[0]), "+f"(c[1]), "+f"(c[2]), "+f"(c[3])
        : "r"(a[0]), "r"(a[1]), "r"(a[2]), "r"(a[3]), "r"(b[0]), "r"(b[1]));
}
__device__ __forceinline__ void cp_async16(uint32_t saddr, const void* g) {
    asm volatile("cp.async.cg.shared.global [%0], [%1], 16;" :: "r"(saddr), "l"(g));
}
__device__ __forceinline__ void cp_commit() { asm volatile("cp.async.commit_group;"); }
__device__ __forceinline__ void ldsm_x4(uint32_t r[4], uint32_t saddr) {
    asm volatile("ldmatrix.sync.aligned.m8n8.x4.shared.b16 {%0,%1,%2,%3}, [%4];"
                 : "=r"(r[0]), "=r"(r[1]), "=r"(r[2]), "=r"(r[3]) : "r"(saddr));
}
__device__ __forceinline__ void ldsm_x2(uint32_t r[2], uint32_t saddr) {
    asm volatile("ldmatrix.sync.aligned.m8n8.x2.shared.b16 {%0,%1}, [%2];"
                 : "=r"(r[0]), "=r"(r[1]) : "r"(saddr));
}

// ============================================================================
// Stage 1: h = x @ W^T + b  (tf32, RN both sides) -> g_hT fp16 transposed
// ============================================================================
#define A_STRIDE 36
__global__ __launch_bounds__(256, 1)
void gemm_lin(const float* __restrict__ x, const float* __restrict__ W,
              const float* __restrict__ bias) {
    float* smem = (float*)dyn_smem;
    float* As0 = smem;
    float* As1 = As0 + BM * A_STRIDE;
    float* Ws0 = As1 + BM * A_STRIDE;
    float* Ws1 = Ws0 + OUTDIM * A_STRIDE;

    const int tid  = threadIdx.x;
    const int lane = tid & 31, wid = tid >> 5;
    const int warpM = wid >> 2, warpN = wid & 3;
    const int bm = blockIdx.x;

    uint32_t sA0 = smem_u32(As0), sA1 = smem_u32(As1);
    uint32_t sW0 = smem_u32(Ws0), sW1 = smem_u32(Ws1);

    float c[4][4][4];
#pragma unroll
    for (int i = 0; i < 4; i++)
#pragma unroll
        for (int j = 0; j < 4; j++)
#pragma unroll
            for (int k = 0; k < 4; k++) c[i][j][k] = 0.0f;

    auto load36 = [&](uint32_t sbase, const float* src, int row0, int k0, int ldK) {
#pragma unroll
        for (int t = 0; t < 4; t++) {
            int idx = tid + t * 256;
            int r = idx >> 3, cc = (idx & 7) << 2;
            cp_async16(sbase + (uint32_t)(r * A_STRIDE + cc) * 4u,
                       src + (size_t)(row0 + r) * ldK + k0 + cc);
        }
    };

    load36(sA0, x, bm * BM, 0, INDIM);
    load36(sW0, W, 0, 0, INDIM);
    cp_commit();

    const int KTL = INDIM / BK; // 8
    for (int kt = 0; kt < KTL; kt++) {
        asm volatile("cp.async.wait_group 0;" ::: "memory");
        __syncthreads();
        if (kt + 1 < KTL) {
            load36(((kt + 1) & 1) ? sA1 : sA0, x, bm * BM, (kt + 1) * BK, INDIM);
            load36(((kt + 1) & 1) ? sW1 : sW0, W, 0, (kt + 1) * BK, INDIM);
            cp_commit();
        }
        const float* As = (kt & 1) ? As1 : As0;
        const float* Ws = (kt & 1) ? Ws1 : Ws0;

#pragma unroll
        for (int kk = 0; kk < BK; kk += 8) {
            uint32_t af[4][4];
#pragma unroll
            for (int mi = 0; mi < 4; mi++) {
                int r  = warpM * 64 + mi * 16 + (lane >> 2);
                int cc = kk + (lane & 3);
                af[mi][0] = f2tf32_rn(As[r * A_STRIDE + cc]);
                af[mi][1] = f2tf32_rn(As[(r + 8) * A_STRIDE + cc]);
                af[mi][2] = f2tf32_rn(As[r * A_STRIDE + cc + 4]);
                af[mi][3] = f2tf32_rn(As[(r + 8) * A_STRIDE + cc + 4]);
            }
            uint32_t bf[4][2];
#pragma unroll
            for (int ni = 0; ni < 4; ni++) {
                int n = warpN * 32 + ni * 8 + (lane >> 2);
                int k = kk + (lane & 3);
                bf[ni][0] = f2tf32_rn(Ws[n * A_STRIDE + k]);
                bf[ni][1] = f2tf32_rn(Ws[n * A_STRIDE + k + 4]);
            }
#pragma unroll
            for (int mi = 0; mi < 4; mi++)
#pragma unroll
                for (int ni = 0; ni < 4; ni++) mma_tf32(c[mi][ni], af[mi], bf[ni]);
        }
        __syncthreads();
    }

    // Epilogue: bias add, fp16-RN, transpose via smem, coalesced store to g_hT.
    __half* st = (__half*)dyn_smem;   // st[o * 136 + n], 128x136 halfs = 34816 B
    __syncthreads();
#pragma unroll
    for (int ni = 0; ni < 4; ni++) {
        int cn = warpN * 32 + ni * 8 + ((lane & 3) << 1);
        float2 bb = *(const float2*)(bias + cn);
#pragma unroll
        for (int mi = 0; mi < 4; mi++) {
            int r = warpM * 64 + mi * 16 + (lane >> 2);
            st[cn * 136 + r]           = __float2half_rn(c[mi][ni][0] + bb.x);
            st[(cn + 1) * 136 + r]     = __float2half_rn(c[mi][ni][1] + bb.y);
            st[cn * 136 + r + 8]       = __float2half_rn(c[mi][ni][2] + bb.x);
            st[(cn + 1) * 136 + r + 8] = __float2half_rn(c[mi][ni][3] + bb.y);
        }
    }
    __syncthreads();
    for (int i = tid; i < 128 * 128; i += 256) {
        int o = i >> 7, n = i & 127;
        g_hT[(size_t)o * NROWS + bm * BM + n] = st[o * 136 + n];
    }
}

// ============================================================================
// Stage 2: out = A_hat @ h, fp16 HMMA m16n8k16.
// 512 threads, 16 warps = 2(M) x 4(N) x 2(K-split). Warp tile 64x32.
// A: R12 path (LDG fp32 -> regs -> fp16 STS stride-40, ldmatrix.x4).
// B: cp.async from g_hT into smem [n][k] (128 x 40 halfs), fragments via
//    ldmatrix.x2 (smem crossbar does the k-scatter; conflict-free pad 40).
// ============================================================================
struct ARegs { float4 v[2]; };   // 8 floats: row tid>>2, k (tid&3)*8 .. +7

__device__ __forceinline__ void ldgA(ARegs& ra, const float* __restrict__ A,
                                     int bm, int kt, int tid) {
    const int row = tid >> 2, kc = (tid & 3) * 8;
    const float* p = A + (size_t)(bm * BM + row) * NROWS + kt * BK + kc;
    ra.v[0] = *(const float4*)p;
    ra.v[1] = *(const float4*)(p + 4);
}

__device__ __forceinline__ void stsA(__half* bufA, const ARegs& ra, int tid) {
    const int row = tid >> 2, kc = (tid & 3) * 8;
    const float* f = (const float*)&ra.v[0];
    __half2 h[4];
#pragma unroll
    for (int j = 0; j < 4; j++) h[j] = __floats2half2_rn(f[2 * j], f[2 * j + 1]);
    uint4 u;
    memcpy(&u, h, 16);
    *(uint4*)&bufA[row * 40 + kc] = u;
}

// B tile cp.async: 128 n-rows x 32 k halfs (64 B) from g_hT row o = n.
// 512 chunks of 16 B, one per thread.
__device__ __forceinline__ void cpB(uint32_t dstBase, int kt, int tid) {
    const int o = tid >> 2, kq = tid & 3;    // 16B chunk within the 64B row
    cp_async16(dstBase + (uint32_t)(o * 80 + kq * 16),
               g_hT + (size_t)o * NROWS + kt * BK + kq * 8);
}

__device__ __forceinline__ void computeTile(uint32_t saBase, uint32_t sbBase,
                                            float c[4][4][4], int lane,
                                            int warpM, int warpN, int warpK) {
    // A fragments: ldmatrix.x4, rows 16-blocked (verified R12 pattern).
    const int rbase = warpM * 64 + ((lane >> 3) & 1) * 8 + (lane & 7);
    const int kloc  = warpK * 16 + (lane >> 4) * 8;
    uint32_t af[4][4];
#pragma unroll
    for (int mi = 0; mi < 4; mi++) {
        uint32_t sa = saBase + (uint32_t)(((rbase + mi * 16) * 40 + kloc) * 2);
        ldsm_x4(af[mi], sa);
    }
    // B fragments: ldmatrix.x2 -- smem rows = n (stride 40 halfs), content = k.
    // matrix0 = k halfs [warpK*16, +8), matrix1 = [+8, +16).
    const int nrow = (lane & 7);
    const int hsel = (lane >> 3) & 1;     // 0: k-lo matrix, 1: k-hi matrix
    uint32_t bf[4][2];
#pragma unroll
    for (int ni = 0; ni < 4; ni++) {
        int n = warpN * 32 + ni * 8 + nrow;
        uint32_t sb = sbBase + (uint32_t)(n * 80 + warpK * 32 + hsel * 16);
        ldsm_x2(bf[ni], sb);
    }
#pragma unroll
    for (int mi = 0; mi < 4; mi++)
#pragma unroll
        for (int ni = 0; ni < 4; ni++) mma_f16(c[mi][ni], af[mi], bf[ni]);
}

__global__ __launch_bounds__(512, 1)
void gemm_aggr(const float* __restrict__ A, float* __restrict__ out) {
    __half* sm = (__half*)dyn_smem;
    __half* bufA[2] = { sm, sm + A_BUF_HALFS };
    const uint32_t sa[2] = { smem_u32(bufA[0]), smem_u32(bufA[1]) };
    const uint32_t sb[2] = { smem_u32(sm + 2 * A_BUF_HALFS),
                             smem_u32(sm + 2 * A_BUF_HALFS + B_BUF_HALFS) };

    const int tid  = threadIdx.x;
    const int lane = tid & 31, wid = tid >> 5;     // wid 0..15
    const int warpK = wid >> 3;                    // 0,1
    const int warpM = (wid >> 2) & 1;              // 0,1
    const int warpN = wid & 3;                     // 0..3
    const int bm = blockIdx.x;

    float c[4][4][4];
#pragma unroll
    for (int i = 0; i < 4; i++)
#pragma unroll
        for (int j = 0; j < 4; j++)
#pragma unroll
            for (int k = 0; k < 4; k++) c[i][j][k] = 0.0f;

    // Prologue: A tile0 -> smem, A tile1 -> regs, B tile0 -> smem.
    ARegs ra;
    {
        ARegs t0;
        ldgA(t0, A, bm, 0, tid);
        cpB(sb[0], 0, tid);
        cp_commit();
        stsA(bufA[0], t0, tid);
        ldgA(ra, A, bm, 1, tid);
        asm volatile("cp.async.wait_group 0;" ::: "memory");
        __syncthreads();
    }

    for (int kt = 0; kt < KT; kt++) {
        const int n1 = (kt + 1 < KT) ? kt + 1 : KT - 1;
        const int n2 = (kt + 2 < KT) ? kt + 2 : KT - 1;

        // Prefetch tile kt+1 into the other buffers.
        cpB(sb[(kt + 1) & 1], n1, tid);
        cp_commit();
        stsA(bufA[(kt + 1) & 1], ra, tid);
        ldgA(ra, A, bm, n2, tid);

        // Compute tile kt (covers cp.async latency of tile kt+1).
        computeTile(sa[kt & 1], sb[kt & 1], c, lane, warpM, warpN, warpK);

        asm volatile("cp.async.wait_group 0;" ::: "memory");
        __syncthreads();
    }

    // ---- split-K reduction: warpK=1 -> smem, warpK=0 adds & stores ----
    float* red = (float*)dyn_smem;        // 8 warps * 2048 floats = 64 KB
    float4* cf4 = (float4*)&c[0][0][0];   // 16 float4 per thread
    __syncthreads();
    if (warpK == 1) {
        float4* dst = (float4*)(red + (wid - 8) * 2048);
#pragma unroll
        for (int i = 0; i < 16; i++) dst[i * 32 + lane] = cf4[i];
    }
    __syncthreads();
    if (warpK == 0) {
        const float4* src = (const float4*)(red + wid * 2048);
#pragma unroll
        for (int i = 0; i < 16; i++) {
            float4 v = src[i * 32 + lane];
            cf4[i].x += v.x; cf4[i].y += v.y; cf4[i].z += v.z; cf4[i].w += v.w;
        }
#pragma unroll
        for (int mi = 0; mi < 4; mi++)
#pragma unroll
            for (int ni = 0; ni < 4; ni++) {
                int r  = bm * BM + warpM * 64 + mi * 16 + (lane >> 2);
                int cn = warpN * 32 + ni * 8 + ((lane & 3) << 1);
                *(float2*)&out[(size_t)r * OUTDIM + cn] =
                    make_float2(c[mi][ni][0], c[mi][ni][1]);
                *(float2*)&out[(size_t)(r + 8) * OUTDIM + cn] =
                    make_float2(c[mi][ni][2], c[mi][ni][3]);
            }
    }
}

static const int SMEM_LIN = (2 * BM * A_STRIDE + 2 * OUTDIM * A_STRIDE) * 4;  // 73728

extern "C" void kernel_launch(void* const* d_in, const int* in_sizes, int n_in,
                              void* d_out, int out_size) {
    const float* x     = (const float*)d_in[0];
    const float* A_hat = (const float*)d_in[1];
    const float* W     = (const float*)d_in[2];
    const float* b     = (const float*)d_in[3];
    float* out = (float*)d_out;

    cudaFuncSetAttribute(gemm_lin,  cudaFuncAttributeMaxDynamicSharedMemorySize, SMEM_LIN);
    cudaFuncSetAttribute(gemm_aggr, cudaFuncAttributeMaxDynamicSharedMemorySize, SMEM_AGGR);

    gemm_lin<<<NROWS / BM, 256, SMEM_LIN>>>(x, W, b);
    gemm_aggr<<<NROWS / BM, 512, SMEM_AGGR>>>(A_hat, out);
}